// round 16
// baseline (speedup 1.0000x reference)
#include <cuda_runtime.h>
#include <math.h>
#include <stdint.h>

#define O_   16
#define C_   64
#define NN   576
#define LL   1024
#define B_   8
#define CH   64
#define NCH  9
#define NT   256       // tiles
#define EPSN 1e-4f
#define WP2  68        // float2 pitch per o row in wb

// Persistent scratch (no cudaMalloc). g_A rewritten bit-identically each
// launch; stale flags benign (idempotent). g_ctr returns to 0 every launch
// (every atomicAdd is matched by the block's exit atomicSub).
__device__ float g_A[O_ * 81];
__device__ int   g_Aflag[O_];
__device__ int   g_ctr;

// ---------------------------------------------------------------------------
#define FMA2(acc_, x_, u_) \
    asm("fma.rn.f32x2 %0, %1, %2, %0;" : "+l"(acc_) : "l"(x_), "l"(u_))
#define MUL2(d_, a_, b_) \
    asm("mul.rn.f32x2 %0, %1, %2;" : "=l"(d_) : "l"(a_), "l"(b_))

__device__ __forceinline__ unsigned long long pk2(float a, float b) {
    unsigned long long r;
    asm("mov.b64 %0, {%1, %2};"
        : "=l"(r) : "r"(__float_as_uint(a)), "r"(__float_as_uint(b)));
    return r;
}
__device__ __forceinline__ void cp16(unsigned dst, const void* src) {
    asm volatile("cp.async.cg.shared.global [%0], [%1], 16;" :: "r"(dst), "l"(src));
}
__device__ __forceinline__ void cp4z(unsigned dst, const void* src, int pred) {
    asm volatile("cp.async.ca.shared.global [%0], [%1], 4, %2;"
                 :: "r"(dst), "l"(src), "r"(pred ? 4 : 0));
}
#define CP_COMMIT() asm volatile("cp.async.commit_group;")
#define CP_WAIT1()  asm volatile("cp.async.wait_group 1;")

// ---------------------------------------------------------------------------
// Blocks 0..15: fp32 symmetric-scaled inverse covariance for channel o.
// EXACT R13 builder. Scratch S = us region; runs before the tile loop.
// ---------------------------------------------------------------------------
__device__ void build_A_block(const float* __restrict__ wgt, float* S, int o, int t) {
    float* sXp   = S;           // 576*9 = 5184
    float* parts = S + 5184;    // 243
    float* Cf    = S + 5440;    // 81
    float* Cm    = S + 5536;    // 171
    float* Dv    = S + 5712;    // 9
    float* fv    = S + 5728;    // 9

    for (int n = t; n < NN; n += 256) {
        float w1 = wgt[(o * NN + n) * 2 + 0];
        float w2 = wgt[(o * NN + n) * 2 + 1];
        float* d = sXp + n * 9;
        d[0] = 1.0f;
        d[1] = w1;        d[2] = w2;
        d[3] = w1 * w1;   d[4] = w2 * w2;
        d[5] = d[3] * w1; d[6] = d[4] * w2;
        d[7] = d[3] * d[3]; d[8] = d[4] * d[4];
    }
    __syncthreads();

    if (t < 243) {
        int pair = t / 3, sl = t - pair * 3;
        int p = pair / 9, q = pair - (pair / 9) * 9;
        float a0 = 0, a1 = 0, a2 = 0, a3 = 0;
        int n0 = sl * 192;
        for (int n = n0; n < n0 + 192; n += 4) {
            a0 += sXp[n * 9 + p]       * sXp[n * 9 + q];
            a1 += sXp[(n + 1) * 9 + p] * sXp[(n + 1) * 9 + q];
            a2 += sXp[(n + 2) * 9 + p] * sXp[(n + 2) * 9 + q];
            a3 += sXp[(n + 3) * 9 + p] * sXp[(n + 3) * 9 + q];
        }
        parts[t] = (a0 + a1) + (a2 + a3);
    }
    __syncthreads();
    if (t < 81) Cf[t] = parts[t * 3] + parts[t * 3 + 1] + parts[t * 3 + 2];
    __syncthreads();
    if (t < 9) Dv[t] = rsqrtf(Cf[t * 9 + t]);
    __syncthreads();
    if (t < 81) {
        int p = t / 9, q = t - 9 * (t / 9);
        Cm[p * 19 + q]     = Cf[t] * Dv[p] * Dv[q];
        Cm[p * 19 + 9 + q] = (p == q) ? 1.0f : 0.0f;
    }
    __syncthreads();

    for (int k = 0; k < 9; k++) {
        if (t < 9) fv[t] = Cm[t * 19 + k];
        __syncthreads();
        if (t < 19) Cm[k * 19 + t] *= (1.0f / fv[k]);
        __syncthreads();
        if (t < 171) {
            int ii = t / 19, jj = t - 19 * (t / 19);
            if (ii != k) Cm[ii * 19 + jj] -= fv[ii] * Cm[k * 19 + jj];
        }
        __syncthreads();
    }
    if (t < 81) {
        int p = t / 9, q = t - 9 * (t / 9);
        g_A[o * 81 + t] = Dv[p] * Cm[p * 19 + 9 + q] * Dv[q];
        __threadfence();
    }
    __syncthreads();
    if (t == 0) *((volatile int*)&g_Aflag[o]) = 1;
    __syncthreads();
}

// ---------------------------------------------------------------------------
// Stage chunk cc of tile (b,i): yb/nb mod-3, wb mod-4. Self-ownership for
// yb/nb: thread t stages exactly floats 4t..4t+3 (+1024) that it combines.
// ---------------------------------------------------------------------------
__device__ __forceinline__ void stage_chunk(
    int cc, int t, int i,
    unsigned yb_b, unsigned nb_b, unsigned wb_b,
    const float* __restrict__ y2b,
    const char*  __restrict__ nzb,
    const char*  __restrict__ wgb)
{
    int bi = cc % 3;
    int b4 = cc & 3;
    #pragma unroll
    for (int g2 = 0; g2 < 2; g2++) {
        int gran = t + g2 * 256;
        int nl = gran >> 3;
        cp16(nb_b + bi * 8192 + gran * 16,
             nzb + ((size_t)(cc * CH + nl)) * (LL * 4) + (gran & 7) * 16);
    }
    #pragma unroll
    for (int g2 = 0; g2 < 2; g2++) {
        int gran = t + g2 * 256;
        int oo = gran >> 5;
        int gi = gran & 31;
        cp16(wb_b + b4 * 8704 + oo * (WP2 * 8) + gi * 16,
             wgb + ((size_t)(oo * NN + cc * CH + gi * 2)) * 8);
    }
    #pragma unroll
    for (int q = 0; q < 8; q++) {
        int k = 4 * t + (q & 3) + (q >> 2) * 1024;
        int n  = cc * CH + (k >> 5);
        int j  = k & 31;
        int ch = n / 9;
        int kk = n - ch * 9;
        int ki = kk / 3, kj = kk - ki * 3;
        int rr = i + ki - 1;
        int cl = j + kj - 1;
        int ok = ((unsigned)rr < 32u) & ((unsigned)cl < 32u);
        const float* srcp = ok ? (y2b + (ch * 32 + rr) * 32 + cl) : y2b;
        cp4z(yb_b + bi * 8192 + k * 4, srcp, ok);
    }
}

// ---------------------------------------------------------------------------
// Persistent fused kernel. Grid 296 (2/SM, all resident). Blocks grab tiles
// (b = tile>>5, i = tile&31) from g_ctr; counter restored at exit.
// Tile body = EXACT R13 (one barrier per chunk; us/yb/nb mod-3, wb mod-4).
// ---------------------------------------------------------------------------
__global__ void __launch_bounds__(256, 2) srn_main(
    const float* __restrict__ y2,
    const float* __restrict__ wgt,
    const float* __restrict__ noise,
    float* __restrict__ out)
{
    extern __shared__ float sm[];
    float*  us  = sm;                     // 3 x 2048
    float*  yb  = sm + 6144;              // 3 x 2048 (stats scratch post-loop)
    float*  nb  = sm + 12288;             // 3 x 2048 (acc scratch post-loop)
    float2* wb  = (float2*)(sm + 18432);  // 4 x 1088 float2
    float*  z0s = sm + 27136;
    float*  s2s = sm + 27168;
    __shared__ int s_tile;

    unsigned sbase = (unsigned)__cvta_generic_to_shared(sm);
    const unsigned yb_b = sbase + 6144 * 4;
    const unsigned nb_b = sbase + 12288 * 4;
    const unsigned wb_b = sbase + 18432 * 4;

    int t = threadIdx.x;
    int h = t >> 7;
    int r = t & 127;
    int o = r >> 3;
    int g = r & 7;
    int j0 = g * 4;

    const char* wgb = (const char*)wgt;

    // builders first (blocks 0..15; scratch = us region, pre-staging)
    if (blockIdx.x < O_)
        build_A_block(wgt, us, blockIdx.x, t);

    int grabs = 0;
    while (true) {
        if (t == 0) s_tile = atomicAdd(&g_ctr, 1);
        __syncthreads();
        int tile = s_tile;
        __syncthreads();            // read done before next iter's write
        if (tile >= NT) break;
        grabs++;

        int b = tile >> 5;
        int i = tile & 31;
        const float* y2b = y2 + b * (C_ * 32 * 32);
        const char*  nzb = (const char*)(noise + (size_t)b * (NN * LL) + (size_t)i * 32);

        unsigned long long acc[16];
        #pragma unroll
        for (int k = 0; k < 16; k++) acc[k] = 0ULL;
        float sa1[4] = {0, 0, 0, 0};
        float sa2[4] = {0, 0, 0, 0};

        stage_chunk(0, t, i, yb_b, nb_b, wb_b, y2b, nzb, wgb);
        CP_COMMIT();
        stage_chunk(1, t, i, yb_b, nb_b, wb_b, y2b, nzb, wgb);
        CP_COMMIT();

        for (int c = 0; c < NCH; c++) {
            int bi = c % 3;
            CP_WAIT1();             // stage(c) landed (c+1 may be in flight)

            // ---- combine own staged floats: u = y2part + eps*noise ----
            #pragma unroll
            for (int hf = 0; hf < 2; hf++) {
                int kb = 4 * t + hf * 1024;
                float4 yv = *(const float4*)(yb + bi * 2048 + kb);
                float4 nv = *(const float4*)(nb + bi * 2048 + kb);
                float v0 = fmaf(EPSN, nv.x, yv.x);
                float v1 = fmaf(EPSN, nv.y, yv.y);
                float v2 = fmaf(EPSN, nv.z, yv.z);
                float v3 = fmaf(EPSN, nv.w, yv.w);
                sa1[0] += v0; sa2[0] += v0 * v0;
                sa1[1] += v1; sa2[1] += v1 * v1;
                sa1[2] += v2; sa2[2] += v2 * v2;
                sa1[3] += v3; sa2[3] += v3 * v3;
                *(float4*)(us + bi * 2048 + kb) = make_float4(v0, v1, v2, v3);
            }

            if (c + 2 < NCH)
                stage_chunk(c + 2, t, i, yb_b, nb_b, wb_b, y2b, nzb, wgb);
            CP_COMMIT();            // one group per iteration (may be empty)
            __syncthreads();        // us[bi] + wb[c&3] visible to all

            // ---- compute over this thread's n-half (32 n) ----
            const float*  up = us + bi * 2048 + h * 32 * 32;
            const float2* wp = wb + (c & 3) * (O_ * WP2) + o * WP2 + h * 32;
            #pragma unroll 4
            for (int nl = 0; nl < 32; nl++) {
                float4 uu = *(const float4*)(up + nl * 32 + j0);
                unsigned long long m1 = *(const unsigned long long*)(wp + nl);
                unsigned long long m2, m3, m4;
                MUL2(m2, m1, m1);
                MUL2(m3, m2, m1);
                MUL2(m4, m2, m2);
                unsigned long long ua = pk2(uu.x, uu.x);
                unsigned long long ub = pk2(uu.y, uu.y);
                unsigned long long uc = pk2(uu.z, uu.z);
                unsigned long long ud = pk2(uu.w, uu.w);
                FMA2(acc[0],  m1, ua); FMA2(acc[1],  m2, ua);
                FMA2(acc[2],  m3, ua); FMA2(acc[3],  m4, ua);
                FMA2(acc[4],  m1, ub); FMA2(acc[5],  m2, ub);
                FMA2(acc[6],  m3, ub); FMA2(acc[7],  m4, ub);
                FMA2(acc[8],  m1, uc); FMA2(acc[9],  m2, uc);
                FMA2(acc[10], m3, uc); FMA2(acc[11], m4, uc);
                FMA2(acc[12], m1, ud); FMA2(acc[13], m2, ud);
                FMA2(acc[14], m3, ud); FMA2(acc[15], m4, ud);
            }
            // no trailing barrier: mod-3 / mod-4 distances close all races
        }

        __syncthreads();    // all compute done before overlaying scratch

        // ---- stats partials (yb) + acc partials (nb) ----
        {
            int slot = t >> 3;
            #pragma unroll
            for (int q = 0; q < 4; q++) {
                int jq = 4 * (t & 7) + q;
                yb[jq * 33 + slot]        = sa1[q];
                yb[1066 + jq * 33 + slot] = sa2[q];
            }
        }
        if (h == 1) {
            #pragma unroll
            for (int k = 0; k < 16; k++) {
                nb[r * 33 + 2 * k]     = __uint_as_float((unsigned)acc[k]);
                nb[r * 33 + 2 * k + 1] = __uint_as_float((unsigned)(acc[k] >> 32));
            }
        }
        __syncthreads();

        if (t < 32) {
            float a = 0.0f, bb = 0.0f;
            #pragma unroll
            for (int s = 0; s < 32; s++) {
                a  += yb[t * 33 + s];
                bb += yb[1066 + t * 33 + s];
            }
            z0s[t] = a;
            s2s[t] = bb;
        }
        __syncthreads();

        if (h == 0) {
            float wv[4][8];
            #pragma unroll
            for (int loc = 0; loc < 4; loc++)
                #pragma unroll
                for (int pp = 0; pp < 4; pp++) {
                    unsigned long long a = acc[loc * 4 + pp];
                    int k = loc * 4 + pp;
                    wv[loc][2 * pp]     = __uint_as_float((unsigned)a)         + nb[r * 33 + 2 * k];
                    wv[loc][2 * pp + 1] = __uint_as_float((unsigned)(a >> 32)) + nb[r * 33 + 2 * k + 1];
                }

            {
                volatile int* fl = g_Aflag + o;
                while (*fl == 0) {}
            }
            __threadfence();

            float w0v[4], wAw[4];
            #pragma unroll
            for (int loc = 0; loc < 4; loc++) {
                w0v[loc] = z0s[j0 + loc];
                wAw[loc] = 0.0f;
            }
            const float* A = g_A + o * 81;
            #pragma unroll
            for (int p = 0; p < 9; p++) {
                float tp[4] = {0.0f, 0.0f, 0.0f, 0.0f};
                #pragma unroll
                for (int q = 0; q < 9; q++) {
                    float a = A[p * 9 + q];
                    #pragma unroll
                    for (int loc = 0; loc < 4; loc++) {
                        float v = (q == 0) ? w0v[loc] : wv[loc][q - 1];
                        tp[loc] = fmaf(a, v, tp[loc]);
                    }
                }
                #pragma unroll
                for (int loc = 0; loc < 4; loc++) {
                    float v = (p == 0) ? w0v[loc] : wv[loc][p - 1];
                    wAw[loc] = fmaf(tp[loc], v, wAw[loc]);
                }
            }

            float4 res;
            #pragma unroll
            for (int loc = 0; loc < 4; loc++) {
                float S2 = s2s[j0 + loc];
                float z0 = w0v[loc];
                float denom = S2 - z0 * z0 * (1.0f / 576.0f);
                float err = (S2 - wAw[loc]) * (575.0f / 576.0f) / denom;
                ((float*)&res)[loc] = expf(-err);
            }
            *(float4*)(out + ((size_t)(b * 16 + o)) * 1024 + i * 32 + j0) = res;
        }
        __syncthreads();    // epilogue scratch reads done before next staging
    }

    // restore counter for graph replay: total adds = NT + gridDim (failed
    // grabs); each block subtracts its grabs + 1.
    if (t == 0) atomicSub(&g_ctr, grabs + 1);
}

// ---------------------------------------------------------------------------
extern "C" void kernel_launch(void* const* d_in, const int* in_sizes, int n_in,
                              void* d_out, int out_size) {
    const float* y2 = nullptr;
    const float* w  = nullptr;
    const float* nz = nullptr;
    for (int k = 0; k < n_in; k++) {
        if      (in_sizes[k] == 524288)  y2 = (const float*)d_in[k];
        else if (in_sizes[k] == 18432)   w  = (const float*)d_in[k];
        else if (in_sizes[k] == 4718592) nz = (const float*)d_in[k];
    }
    if (!y2 || !w || !nz) {
        y2 = (const float*)d_in[0];
        w  = (const float*)d_in[1];
        nz = (const float*)d_in[2];
    }

    const int smem_bytes = 27200 * 4;   // 108800 B
    cudaFuncSetAttribute(srn_main, cudaFuncAttributeMaxDynamicSharedMemorySize, smem_bytes);
    srn_main<<<296, 256, smem_bytes>>>(y2, w, nz, (float*)d_out);
}

// round 17
// speedup vs baseline: 115.3733x; 115.3733x over previous
#include <cuda_runtime.h>
#include <math.h>
#include <stdint.h>

#define O_   16
#define C_   64
#define NN   576
#define LL   1024
#define B_   8
#define CH   64
#define NCH  9
#define NT   256       // tiles
#define EPSN 1e-4f
#define WP2  68        // float2 pitch per o row in wb

// Persistent scratch (no cudaMalloc). g_A rewritten bit-identically each
// launch; stale flags benign (idempotent). g_ctr/g_done reset by the LAST
// block to exit (race-free: unique by atomicity) -> clean state per replay.
__device__ float g_A[O_ * 81];
__device__ int   g_Aflag[O_];
__device__ int   g_ctr;
__device__ int   g_done;

// ---------------------------------------------------------------------------
#define FMA2(acc_, x_, u_) \
    asm("fma.rn.f32x2 %0, %1, %2, %0;" : "+l"(acc_) : "l"(x_), "l"(u_))
#define MUL2(d_, a_, b_) \
    asm("mul.rn.f32x2 %0, %1, %2;" : "=l"(d_) : "l"(a_), "l"(b_))

__device__ __forceinline__ unsigned long long pk2(float a, float b) {
    unsigned long long r;
    asm("mov.b64 %0, {%1, %2};"
        : "=l"(r) : "r"(__float_as_uint(a)), "r"(__float_as_uint(b)));
    return r;
}
__device__ __forceinline__ void cp16(unsigned dst, const void* src) {
    asm volatile("cp.async.cg.shared.global [%0], [%1], 16;" :: "r"(dst), "l"(src));
}
__device__ __forceinline__ void cp4z(unsigned dst, const void* src, int pred) {
    asm volatile("cp.async.ca.shared.global [%0], [%1], 4, %2;"
                 :: "r"(dst), "l"(src), "r"(pred ? 4 : 0));
}
#define CP_COMMIT() asm volatile("cp.async.commit_group;")
#define CP_WAIT1()  asm volatile("cp.async.wait_group 1;")

// ---------------------------------------------------------------------------
// Blocks 0..15: fp32 symmetric-scaled inverse covariance for channel o.
// EXACT R13 builder. Scratch S = us region; runs before the tile loop.
// ---------------------------------------------------------------------------
__device__ void build_A_block(const float* __restrict__ wgt, float* S, int o, int t) {
    float* sXp   = S;           // 576*9 = 5184
    float* parts = S + 5184;    // 243
    float* Cf    = S + 5440;    // 81
    float* Cm    = S + 5536;    // 171
    float* Dv    = S + 5712;    // 9
    float* fv    = S + 5728;    // 9

    for (int n = t; n < NN; n += 256) {
        float w1 = wgt[(o * NN + n) * 2 + 0];
        float w2 = wgt[(o * NN + n) * 2 + 1];
        float* d = sXp + n * 9;
        d[0] = 1.0f;
        d[1] = w1;        d[2] = w2;
        d[3] = w1 * w1;   d[4] = w2 * w2;
        d[5] = d[3] * w1; d[6] = d[4] * w2;
        d[7] = d[3] * d[3]; d[8] = d[4] * d[4];
    }
    __syncthreads();

    if (t < 243) {
        int pair = t / 3, sl = t - pair * 3;
        int p = pair / 9, q = pair - (pair / 9) * 9;
        float a0 = 0, a1 = 0, a2 = 0, a3 = 0;
        int n0 = sl * 192;
        for (int n = n0; n < n0 + 192; n += 4) {
            a0 += sXp[n * 9 + p]       * sXp[n * 9 + q];
            a1 += sXp[(n + 1) * 9 + p] * sXp[(n + 1) * 9 + q];
            a2 += sXp[(n + 2) * 9 + p] * sXp[(n + 2) * 9 + q];
            a3 += sXp[(n + 3) * 9 + p] * sXp[(n + 3) * 9 + q];
        }
        parts[t] = (a0 + a1) + (a2 + a3);
    }
    __syncthreads();
    if (t < 81) Cf[t] = parts[t * 3] + parts[t * 3 + 1] + parts[t * 3 + 2];
    __syncthreads();
    if (t < 9) Dv[t] = rsqrtf(Cf[t * 9 + t]);
    __syncthreads();
    if (t < 81) {
        int p = t / 9, q = t - 9 * (t / 9);
        Cm[p * 19 + q]     = Cf[t] * Dv[p] * Dv[q];
        Cm[p * 19 + 9 + q] = (p == q) ? 1.0f : 0.0f;
    }
    __syncthreads();

    for (int k = 0; k < 9; k++) {
        if (t < 9) fv[t] = Cm[t * 19 + k];
        __syncthreads();
        if (t < 19) Cm[k * 19 + t] *= (1.0f / fv[k]);
        __syncthreads();
        if (t < 171) {
            int ii = t / 19, jj = t - 19 * (t / 19);
            if (ii != k) Cm[ii * 19 + jj] -= fv[ii] * Cm[k * 19 + jj];
        }
        __syncthreads();
    }
    if (t < 81) {
        int p = t / 9, q = t - 9 * (t / 9);
        g_A[o * 81 + t] = Dv[p] * Cm[p * 19 + 9 + q] * Dv[q];
        __threadfence();
    }
    __syncthreads();
    if (t == 0) *((volatile int*)&g_Aflag[o]) = 1;
    __syncthreads();
}

// ---------------------------------------------------------------------------
// Stage chunk cc of tile (b,i): yb/nb mod-3, wb mod-4. Self-ownership for
// yb/nb: thread t stages exactly floats 4t..4t+3 (+1024) that it combines.
// ---------------------------------------------------------------------------
__device__ __forceinline__ void stage_chunk(
    int cc, int t, int i,
    unsigned yb_b, unsigned nb_b, unsigned wb_b,
    const float* __restrict__ y2b,
    const char*  __restrict__ nzb,
    const char*  __restrict__ wgb)
{
    int bi = cc % 3;
    int b4 = cc & 3;
    #pragma unroll
    for (int g2 = 0; g2 < 2; g2++) {
        int gran = t + g2 * 256;
        int nl = gran >> 3;
        cp16(nb_b + bi * 8192 + gran * 16,
             nzb + ((size_t)(cc * CH + nl)) * (LL * 4) + (gran & 7) * 16);
    }
    #pragma unroll
    for (int g2 = 0; g2 < 2; g2++) {
        int gran = t + g2 * 256;
        int oo = gran >> 5;
        int gi = gran & 31;
        cp16(wb_b + b4 * 8704 + oo * (WP2 * 8) + gi * 16,
             wgb + ((size_t)(oo * NN + cc * CH + gi * 2)) * 8);
    }
    #pragma unroll
    for (int q = 0; q < 8; q++) {
        int k = 4 * t + (q & 3) + (q >> 2) * 1024;
        int n  = cc * CH + (k >> 5);
        int j  = k & 31;
        int ch = n / 9;
        int kk = n - ch * 9;
        int ki = kk / 3, kj = kk - ki * 3;
        int rr = i + ki - 1;
        int cl = j + kj - 1;
        int ok = ((unsigned)rr < 32u) & ((unsigned)cl < 32u);
        const float* srcp = ok ? (y2b + (ch * 32 + rr) * 32 + cl) : y2b;
        cp4z(yb_b + bi * 8192 + k * 4, srcp, ok);
    }
}

// ---------------------------------------------------------------------------
// Persistent fused kernel. Grid 296 (2/SM). Blocks grab tiles from g_ctr;
// the LAST block to exit resets g_ctr/g_done for the next graph replay.
// Tile body = EXACT R13 (one barrier per chunk; us/yb/nb mod-3, wb mod-4).
// ---------------------------------------------------------------------------
__global__ void __launch_bounds__(256, 2) srn_main(
    const float* __restrict__ y2,
    const float* __restrict__ wgt,
    const float* __restrict__ noise,
    float* __restrict__ out)
{
    extern __shared__ float sm[];
    float*  us  = sm;                     // 3 x 2048
    float*  yb  = sm + 6144;              // 3 x 2048 (stats scratch post-loop)
    float*  nb  = sm + 12288;             // 3 x 2048 (acc scratch post-loop)
    float2* wb  = (float2*)(sm + 18432);  // 4 x 1088 float2
    float*  z0s = sm + 27136;
    float*  s2s = sm + 27168;
    __shared__ int s_tile;

    unsigned sbase = (unsigned)__cvta_generic_to_shared(sm);
    const unsigned yb_b = sbase + 6144 * 4;
    const unsigned nb_b = sbase + 12288 * 4;
    const unsigned wb_b = sbase + 18432 * 4;

    int t = threadIdx.x;
    int h = t >> 7;
    int r = t & 127;
    int o = r >> 3;
    int g = r & 7;
    int j0 = g * 4;

    const char* wgb = (const char*)wgt;

    // builders first (blocks 0..15; scratch = us region, pre-staging)
    if (blockIdx.x < O_)
        build_A_block(wgt, us, blockIdx.x, t);

    while (true) {
        if (t == 0) s_tile = atomicAdd(&g_ctr, 1);
        __syncthreads();
        int tile = s_tile;
        __syncthreads();            // read done before next iter's write
        if (tile >= NT) break;

        int b = tile >> 5;
        int i = tile & 31;
        const float* y2b = y2 + b * (C_ * 32 * 32);
        const char*  nzb = (const char*)(noise + (size_t)b * (NN * LL) + (size_t)i * 32);

        unsigned long long acc[16];
        #pragma unroll
        for (int k = 0; k < 16; k++) acc[k] = 0ULL;
        float sa1[4] = {0, 0, 0, 0};
        float sa2[4] = {0, 0, 0, 0};

        stage_chunk(0, t, i, yb_b, nb_b, wb_b, y2b, nzb, wgb);
        CP_COMMIT();
        stage_chunk(1, t, i, yb_b, nb_b, wb_b, y2b, nzb, wgb);
        CP_COMMIT();

        for (int c = 0; c < NCH; c++) {
            int bi = c % 3;
            CP_WAIT1();             // stage(c) landed (c+1 may be in flight)

            // ---- combine own staged floats: u = y2part + eps*noise ----
            #pragma unroll
            for (int hf = 0; hf < 2; hf++) {
                int kb = 4 * t + hf * 1024;
                float4 yv = *(const float4*)(yb + bi * 2048 + kb);
                float4 nv = *(const float4*)(nb + bi * 2048 + kb);
                float v0 = fmaf(EPSN, nv.x, yv.x);
                float v1 = fmaf(EPSN, nv.y, yv.y);
                float v2 = fmaf(EPSN, nv.z, yv.z);
                float v3 = fmaf(EPSN, nv.w, yv.w);
                sa1[0] += v0; sa2[0] += v0 * v0;
                sa1[1] += v1; sa2[1] += v1 * v1;
                sa1[2] += v2; sa2[2] += v2 * v2;
                sa1[3] += v3; sa2[3] += v3 * v3;
                *(float4*)(us + bi * 2048 + kb) = make_float4(v0, v1, v2, v3);
            }

            if (c + 2 < NCH)
                stage_chunk(c + 2, t, i, yb_b, nb_b, wb_b, y2b, nzb, wgb);
            CP_COMMIT();            // one group per iteration (may be empty)
            __syncthreads();        // us[bi] + wb[c&3] visible to all

            // ---- compute over this thread's n-half (32 n) ----
            const float*  up = us + bi * 2048 + h * 32 * 32;
            const float2* wp = wb + (c & 3) * (O_ * WP2) + o * WP2 + h * 32;
            #pragma unroll 4
            for (int nl = 0; nl < 32; nl++) {
                float4 uu = *(const float4*)(up + nl * 32 + j0);
                unsigned long long m1 = *(const unsigned long long*)(wp + nl);
                unsigned long long m2, m3, m4;
                MUL2(m2, m1, m1);
                MUL2(m3, m2, m1);
                MUL2(m4, m2, m2);
                unsigned long long ua = pk2(uu.x, uu.x);
                unsigned long long ub = pk2(uu.y, uu.y);
                unsigned long long uc = pk2(uu.z, uu.z);
                unsigned long long ud = pk2(uu.w, uu.w);
                FMA2(acc[0],  m1, ua); FMA2(acc[1],  m2, ua);
                FMA2(acc[2],  m3, ua); FMA2(acc[3],  m4, ua);
                FMA2(acc[4],  m1, ub); FMA2(acc[5],  m2, ub);
                FMA2(acc[6],  m3, ub); FMA2(acc[7],  m4, ub);
                FMA2(acc[8],  m1, uc); FMA2(acc[9],  m2, uc);
                FMA2(acc[10], m3, uc); FMA2(acc[11], m4, uc);
                FMA2(acc[12], m1, ud); FMA2(acc[13], m2, ud);
                FMA2(acc[14], m3, ud); FMA2(acc[15], m4, ud);
            }
            // no trailing barrier: mod-3 / mod-4 distances close all races
        }

        __syncthreads();    // all compute done before overlaying scratch

        // ---- stats partials (yb) + acc partials (nb) ----
        {
            int slot = t >> 3;
            #pragma unroll
            for (int q = 0; q < 4; q++) {
                int jq = 4 * (t & 7) + q;
                yb[jq * 33 + slot]        = sa1[q];
                yb[1066 + jq * 33 + slot] = sa2[q];
            }
        }
        if (h == 1) {
            #pragma unroll
            for (int k = 0; k < 16; k++) {
                nb[r * 33 + 2 * k]     = __uint_as_float((unsigned)acc[k]);
                nb[r * 33 + 2 * k + 1] = __uint_as_float((unsigned)(acc[k] >> 32));
            }
        }
        __syncthreads();

        if (t < 32) {
            float a = 0.0f, bb = 0.0f;
            #pragma unroll
            for (int s = 0; s < 32; s++) {
                a  += yb[t * 33 + s];
                bb += yb[1066 + t * 33 + s];
            }
            z0s[t] = a;
            s2s[t] = bb;
        }
        __syncthreads();

        if (h == 0) {
            float wv[4][8];
            #pragma unroll
            for (int loc = 0; loc < 4; loc++)
                #pragma unroll
                for (int pp = 0; pp < 4; pp++) {
                    unsigned long long a = acc[loc * 4 + pp];
                    int k = loc * 4 + pp;
                    wv[loc][2 * pp]     = __uint_as_float((unsigned)a)         + nb[r * 33 + 2 * k];
                    wv[loc][2 * pp + 1] = __uint_as_float((unsigned)(a >> 32)) + nb[r * 33 + 2 * k + 1];
                }

            {
                volatile int* fl = g_Aflag + o;
                while (*fl == 0) {}
            }
            __threadfence();

            float w0v[4], wAw[4];
            #pragma unroll
            for (int loc = 0; loc < 4; loc++) {
                w0v[loc] = z0s[j0 + loc];
                wAw[loc] = 0.0f;
            }
            const float* A = g_A + o * 81;
            #pragma unroll
            for (int p = 0; p < 9; p++) {
                float tp[4] = {0.0f, 0.0f, 0.0f, 0.0f};
                #pragma unroll
                for (int q = 0; q < 9; q++) {
                    float a = A[p * 9 + q];
                    #pragma unroll
                    for (int loc = 0; loc < 4; loc++) {
                        float v = (q == 0) ? w0v[loc] : wv[loc][q - 1];
                        tp[loc] = fmaf(a, v, tp[loc]);
                    }
                }
                #pragma unroll
                for (int loc = 0; loc < 4; loc++) {
                    float v = (p == 0) ? w0v[loc] : wv[loc][p - 1];
                    wAw[loc] = fmaf(tp[loc], v, wAw[loc]);
                }
            }

            float4 res;
            #pragma unroll
            for (int loc = 0; loc < 4; loc++) {
                float S2 = s2s[j0 + loc];
                float z0 = w0v[loc];
                float denom = S2 - z0 * z0 * (1.0f / 576.0f);
                float err = (S2 - wAw[loc]) * (575.0f / 576.0f) / denom;
                ((float*)&res)[loc] = expf(-err);
            }
            *(float4*)(out + ((size_t)(b * 16 + o)) * 1024 + i * 32 + j0) = res;
        }
        __syncthreads();    // epilogue scratch reads done before next staging
    }

    // Last-block-out resets the counters for the next graph replay.
    // All of this block's g_ctr adds precede the fence; the unique block
    // observing gridDim-1 knows every other block's adds are complete.
    if (t == 0) {
        __threadfence();
        int old = atomicAdd(&g_done, 1);
        if (old == (int)gridDim.x - 1) {
            g_ctr  = 0;
            g_done = 0;
            __threadfence();
        }
    }
}

// ---------------------------------------------------------------------------
extern "C" void kernel_launch(void* const* d_in, const int* in_sizes, int n_in,
                              void* d_out, int out_size) {
    const float* y2 = nullptr;
    const float* w  = nullptr;
    const float* nz = nullptr;
    for (int k = 0; k < n_in; k++) {
        if      (in_sizes[k] == 524288)  y2 = (const float*)d_in[k];
        else if (in_sizes[k] == 18432)   w  = (const float*)d_in[k];
        else if (in_sizes[k] == 4718592) nz = (const float*)d_in[k];
    }
    if (!y2 || !w || !nz) {
        y2 = (const float*)d_in[0];
        w  = (const float*)d_in[1];
        nz = (const float*)d_in[2];
    }

    const int smem_bytes = 27200 * 4;   // 108800 B
    cudaFuncSetAttribute(srn_main, cudaFuncAttributeMaxDynamicSharedMemorySize, smem_bytes);
    srn_main<<<296, 256, smem_bytes>>>(y2, w, nz, (float*)d_out);
}